// round 1
// baseline (speedup 1.0000x reference)
#include <cuda_runtime.h>

#define E   512
#define HEADS 2
#define HD  256
#define NT  64   // num texts
#define NW  32   // words per text
#define NV  128  // num videos
#define NF  64   // frames per video
#define ACHUNKS 4
#define A_PER_CHUNK (NV / ACHUNKS)   // 32

// ------------------- device scratch (no allocs allowed) -------------------
__device__ float g_Q[NT * NW * E];            // 2048 x 512  (4 MB)
__device__ float g_K[NV * NF * E];            // 8192 x 512  (16 MB)
__device__ float g_V[NV * NF * E];            // 8192 x 512  (16 MB)
__device__ float g_part[ACHUNKS][NT * NW * E];// 4 x 2048 x 512 (16 MB)

// ---------------------------------------------------------------------------
// GEMM: C[M,512] = (sum over nparts slices of A)[M,512] @ W[512,512]^T + bias
// Block tile 128(M) x 64(N), BK=16, 256 threads, 8x4 register microtile.
// ---------------------------------------------------------------------------
__global__ __launch_bounds__(256) void gemm_bias_kernel(
    const float* __restrict__ A, const float* __restrict__ W,
    const float* __restrict__ bias, float* __restrict__ C,
    int nparts, int partStride)
{
    __shared__ float As[16][128];
    __shared__ float Bs[16][64];

    const int tid = threadIdx.x;
    const int m0 = blockIdx.y * 128;
    const int n0 = blockIdx.x * 64;
    const int tx = tid & 15;        // 16 n-groups
    const int ty = tid >> 4;        // 16 m-groups
    const int lr = tid >> 2;        // 0..63 load row
    const int lc = (tid & 3) * 4;   // 0,4,8,12 load col

    float acc[8][4];
#pragma unroll
    for (int i = 0; i < 8; i++)
#pragma unroll
        for (int j = 0; j < 4; j++) acc[i][j] = 0.0f;

    for (int k0 = 0; k0 < E; k0 += 16) {
        float4 a0 = make_float4(0.f, 0.f, 0.f, 0.f);
        float4 a1 = make_float4(0.f, 0.f, 0.f, 0.f);
        for (int p = 0; p < nparts; p++) {
            const float* Ap = A + (size_t)p * (size_t)partStride;
            float4 t0 = *(const float4*)&Ap[(size_t)(m0 + lr) * E + k0 + lc];
            float4 t1 = *(const float4*)&Ap[(size_t)(m0 + lr + 64) * E + k0 + lc];
            a0.x += t0.x; a0.y += t0.y; a0.z += t0.z; a0.w += t0.w;
            a1.x += t1.x; a1.y += t1.y; a1.z += t1.z; a1.w += t1.w;
        }
        float4 b0 = *(const float4*)&W[(size_t)(n0 + lr) * E + k0 + lc];

        __syncthreads();
        As[lc + 0][lr] = a0.x; As[lc + 1][lr] = a0.y;
        As[lc + 2][lr] = a0.z; As[lc + 3][lr] = a0.w;
        As[lc + 0][lr + 64] = a1.x; As[lc + 1][lr + 64] = a1.y;
        As[lc + 2][lr + 64] = a1.z; As[lc + 3][lr + 64] = a1.w;
        Bs[lc + 0][lr] = b0.x; Bs[lc + 1][lr] = b0.y;
        Bs[lc + 2][lr] = b0.z; Bs[lc + 3][lr] = b0.w;
        __syncthreads();

#pragma unroll
        for (int kk = 0; kk < 16; kk++) {
            float4 x0 = *(const float4*)&As[kk][ty * 8];
            float4 x1 = *(const float4*)&As[kk][ty * 8 + 4];
            float4 y  = *(const float4*)&Bs[kk][tx * 4];
            float am[8] = {x0.x, x0.y, x0.z, x0.w, x1.x, x1.y, x1.z, x1.w};
            float bn[4] = {y.x, y.y, y.z, y.w};
#pragma unroll
            for (int i = 0; i < 8; i++)
#pragma unroll
                for (int j = 0; j < 4; j++) acc[i][j] += am[i] * bn[j];
        }
    }

    float4 bv = *(const float4*)&bias[n0 + tx * 4];
#pragma unroll
    for (int i = 0; i < 8; i++) {
        float4 o;
        o.x = acc[i][0] + bv.x;
        o.y = acc[i][1] + bv.y;
        o.z = acc[i][2] + bv.z;
        o.w = acc[i][3] + bv.w;
        *(float4*)&C[(size_t)(m0 + ty * 8 + i) * E + n0 + tx * 4] = o;
    }
}

// ---------------------------------------------------------------------------
// Attention: block = (b, h, a-chunk). Loops over 32 videos, accumulating
//   attn[t,d] += sum_v V[a,v,h,d] * softmax_v(K_a Q_b^T / 16)[v,t] / 128
// in registers; writes its own slice of g_part (no atomics).
// Thread layouts:
//   logits: warp w -> frames v in [8w, 8w+8), lane -> t   (Q transposed in smem)
//   attn:   warp w -> t in [4w, 4w+4), lane -> d = {4*lane, 4*lane+128} (+0..3)
// ---------------------------------------------------------------------------
#define SMEM_FLOATS (NF*HD + NF*HD + HD*33 + NF*NW)
#define SMEM_BYTES  (SMEM_FLOATS * 4)

__global__ __launch_bounds__(256, 1) void attn_kernel()
{
    extern __shared__ float sm[];
    float* Ks  = sm;                       // [64][256]
    float* Vs  = sm + NF * HD;             // [64][256]
    float* Qst = sm + 2 * NF * HD;         // [256][33] transposed, padded
    float* Ls  = Qst + HD * 33;            // [64][32] logits -> weights

    const int b   = blockIdx.x;
    const int h   = blockIdx.y;
    const int ac  = blockIdx.z;
    const int tid = threadIdx.x;
    const int warp = tid >> 5;
    const int lane = tid & 31;

    // Load Q_b,h transposed into smem (once per block)
    for (int idx = tid; idx < NW * HD / 4; idx += 256) {
        int t  = idx >> 6;           // 0..31
        int d4 = (idx & 63) * 4;     // 0..252
        float4 q = *(const float4*)&g_Q[(size_t)(b * NW + t) * E + h * HD + d4];
        Qst[(d4 + 0) * 33 + t] = q.x;
        Qst[(d4 + 1) * 33 + t] = q.y;
        Qst[(d4 + 2) * 33 + t] = q.z;
        Qst[(d4 + 3) * 33 + t] = q.w;
    }

    float accA[4][4], accB[4][4];
#pragma unroll
    for (int j = 0; j < 4; j++)
#pragma unroll
        for (int i = 0; i < 4; i++) { accA[j][i] = 0.0f; accB[j][i] = 0.0f; }

    const int t0 = warp * 4;   // attn-phase t group
    const int v0 = warp * 8;   // logits-phase v group
    const int dA = lane * 4;   // attn-phase d group

    const int aBeg = ac * A_PER_CHUNK;
    for (int a = aBeg; a < aBeg + A_PER_CHUNK; a++) {
        __syncthreads();   // prior attn-phase readers of Vs/Ls done; Qst ready
        // load K_a,h and V_a,h tiles
        for (int idx = tid; idx < NF * HD / 4; idx += 256) {
            int f  = idx >> 6;
            int d4 = (idx & 63) * 4;
            size_t g = (size_t)(a * NF + f) * E + h * HD + d4;
            *(float4*)&Ks[f * HD + d4] = *(const float4*)&g_K[g];
            *(float4*)&Vs[f * HD + d4] = *(const float4*)&g_V[g];
        }
        __syncthreads();

        // logits: L[v][t] = (K_v . Q_t) / 16
        {
            float lacc[8];
#pragma unroll
            for (int i = 0; i < 8; i++) lacc[i] = 0.0f;
            for (int d = 0; d < HD; d += 4) {
                float q0 = Qst[(d + 0) * 33 + lane];
                float q1 = Qst[(d + 1) * 33 + lane];
                float q2 = Qst[(d + 2) * 33 + lane];
                float q3 = Qst[(d + 3) * 33 + lane];
#pragma unroll
                for (int i = 0; i < 8; i++) {
                    float4 kf = *(const float4*)&Ks[(v0 + i) * HD + d];
                    lacc[i] += kf.x * q0 + kf.y * q1 + kf.z * q2 + kf.w * q3;
                }
            }
#pragma unroll
            for (int i = 0; i < 8; i++)
                Ls[(v0 + i) * NW + lane] = lacc[i] * 0.0625f;
        }
        __syncthreads();

        // softmax over v per t (warp 0, lane = t), fold in 1/128 for the mean
        if (warp == 0) {
            float m = -1e30f;
            for (int v = 0; v < NF; v++) m = fmaxf(m, Ls[v * NW + lane]);
            float s = 0.0f;
            for (int v = 0; v < NF; v++) {
                float e = __expf(Ls[v * NW + lane] - m);
                Ls[v * NW + lane] = e;
                s += e;
            }
            float inv = (1.0f / 128.0f) / s;
            for (int v = 0; v < NF; v++) Ls[v * NW + lane] *= inv;
        }
        __syncthreads();

        // attn accumulate: acc[t][d] += V[v][d] * w[v][t]
        for (int v = 0; v < NF; v++) {
            float4 va = *(const float4*)&Vs[v * HD + dA];
            float4 vb = *(const float4*)&Vs[v * HD + 128 + dA];
            float wv[4];
            wv[0] = Ls[v * NW + t0 + 0];
            wv[1] = Ls[v * NW + t0 + 1];
            wv[2] = Ls[v * NW + t0 + 2];
            wv[3] = Ls[v * NW + t0 + 3];
            float vaA[4] = {va.x, va.y, va.z, va.w};
            float vbA[4] = {vb.x, vb.y, vb.z, vb.w};
#pragma unroll
            for (int j = 0; j < 4; j++)
#pragma unroll
                for (int i = 0; i < 4; i++) {
                    accA[j][i] += vaA[i] * wv[j];
                    accB[j][i] += vbA[i] * wv[j];
                }
        }
    }

    // write partial result; layout matches torch reshape (h*8192 + t*256 + d)
    float* dst = &g_part[ac][(size_t)b * (NW * E) + h * (NW * HD)];
#pragma unroll
    for (int j = 0; j < 4; j++) {
        int t = t0 + j;
        *(float4*)&dst[t * HD + dA] =
            make_float4(accA[j][0], accA[j][1], accA[j][2], accA[j][3]);
        *(float4*)&dst[t * HD + 128 + dA] =
            make_float4(accB[j][0], accB[j][1], accB[j][2], accB[j][3]);
    }
}

// ---------------------------------------------------------------------------
extern "C" void kernel_launch(void* const* d_in, const int* in_sizes, int n_in,
                              void* d_out, int out_size)
{
    const float* text  = (const float*)d_in[0];
    const float* video = (const float*)d_in[1];
    const float* Wq = (const float*)d_in[2];
    const float* bq = (const float*)d_in[3];
    const float* Wk = (const float*)d_in[4];
    const float* bk = (const float*)d_in[5];
    const float* Wv = (const float*)d_in[6];
    const float* bv = (const float*)d_in[7];
    const float* Wo = (const float*)d_in[8];
    const float* bo = (const float*)d_in[9];
    float* out = (float*)d_out;

    float *Qp, *Kp, *Vp, *Pp;
    cudaGetSymbolAddress((void**)&Qp, g_Q);
    cudaGetSymbolAddress((void**)&Kp, g_K);
    cudaGetSymbolAddress((void**)&Vp, g_V);
    cudaGetSymbolAddress((void**)&Pp, g_part);

    cudaFuncSetAttribute(attn_kernel,
                         cudaFuncAttributeMaxDynamicSharedMemorySize, SMEM_BYTES);

    dim3 thr(256);
    // Projections: Q [2048x512], K [8192x512], V [8192x512]
    gemm_bias_kernel<<<dim3(8, 16), thr>>>(text,  Wq, bq, Qp, 1, 0);
    gemm_bias_kernel<<<dim3(8, 64), thr>>>(video, Wk, bk, Kp, 1, 0);
    gemm_bias_kernel<<<dim3(8, 64), thr>>>(video, Wv, bv, Vp, 1, 0);

    // Attention with register-accumulated mean over videos (4 a-chunks)
    attn_kernel<<<dim3(NT, HEADS, ACHUNKS), thr, SMEM_BYTES>>>();

    // Output projection; sums the 4 partials during the A-load
    gemm_bias_kernel<<<dim3(8, 16), thr>>>(Pp, Wo, bo, out, ACHUNKS, NT * NW * E);
}

// round 4
// speedup vs baseline: 3.2569x; 3.2569x over previous
#include <cuda_runtime.h>
#include <cstdint>

#define E    512
#define HD   256
#define NT   64
#define NW   32
#define NV   128
#define NF   64
#define MTXT 2048
#define MVID 8192
#define NSPLIT 8
#define KSPL  1024

#define BM 128
#define BN 128
#define BK 32
#define SSTR 36   // smem row stride in floats

// ---------------- device scratch ----------------
__device__ float g_Q[(long long)MTXT * E];
__device__ float g_K[(long long)MVID * E];
__device__ float g_Vt[2ll * HD * MVID];
__device__ float g_L[2ll * MVID * MTXT];
__device__ float g_Wt[2ll * MTXT * MVID];
__device__ float g_part[(long long)NSPLIT * MTXT * E];

__device__ __forceinline__ float rntf32(float x) {
    uint32_t u; asm("cvt.rna.tf32.f32 %0, %1;" : "=r"(u) : "f"(x));
    return __uint_as_float(u);
}

__device__ __forceinline__ void mma_tf32(float* c, const uint32_t* a, const uint32_t* b) {
    asm volatile(
        "mma.sync.aligned.m16n8k8.row.col.f32.tf32.tf32.f32 "
        "{%0,%1,%2,%3}, {%4,%5,%6,%7}, {%8,%9}, {%0,%1,%2,%3};"
        : "+f"(c[0]), "+f"(c[1]), "+f"(c[2]), "+f"(c[3])
        : "r"(a[0]), "r"(a[1]), "r"(a[2]), "r"(a[3]), "r"(b[0]), "r"(b[1]));
}

// ---------------------------------------------------------------------------
// tf32 mma.sync GEMM: D[m,n] = sum_k A[m,k] * B[n,k]  (both K-major)
// epi: 0 = bias + row-major store       1 = Vt transpose store
//      2 = scale + row-major store      3 = attn scatter (torch reshape)
// ---------------------------------------------------------------------------
__global__ __launch_bounds__(256, 2) void gemm_mma(
    const float* __restrict__ A, int lda, long long aH, long long aS,
    const float* __restrict__ B, int ldb, long long bH, long long bS,
    const float* __restrict__ bias, float* __restrict__ D,
    int K, int nsplit, int nparts, long long pStride,
    int epi, int ldd, long long dH, float scale)
{
    __shared__ float As[BM * SSTR];
    __shared__ float Bs[BN * SSTR];

    const int tid  = threadIdx.x;
    const int warp = tid >> 5;
    const int lane = tid & 31;
    const int gid  = lane >> 2;   // 0..7
    const int tig  = lane & 3;    // 0..3
    const int wm   = warp & 1;    // 2 warps in m
    const int wn   = warp >> 1;   // 4 warps in n

    const int zh = blockIdx.z / nsplit;
    const int zs = blockIdx.z % nsplit;
    const int m0 = blockIdx.y * BM;
    const int n0 = blockIdx.x * BN;
    const float* Ab = A + zh * aH + zs * aS;
    const float* Bb = B + zh * bH + zs * bS;

    float acc[4][4][4];
#pragma unroll
    for (int i = 0; i < 4; i++)
#pragma unroll
        for (int j = 0; j < 4; j++)
#pragma unroll
            for (int c = 0; c < 4; c++) acc[i][j][c] = 0.0f;

    const int lm = tid >> 3;           // 0..31 base load row
    const int lk = (tid & 7) << 2;     // 0,4,...,28 load col

    const int S = K / BK;
    for (int s = 0; s < S; s++) {
        const int k0 = s * BK;
        // -------- load full 128-row A and B tiles (4 rows-groups each) ----
#pragma unroll
        for (int i = 0; i < 4; i++) {
            const int r = lm + i * 32;
            const float* ap = Ab + (long long)(m0 + r) * lda + k0 + lk;
            float4 v = *(const float4*)ap;
            for (int p = 1; p < nparts; p++) {
                float4 w = *(const float4*)(ap + (long long)p * pStride);
                v.x += w.x; v.y += w.y; v.z += w.z; v.w += w.w;
            }
            *(float4*)&As[r * SSTR + lk] =
                make_float4(rntf32(v.x), rntf32(v.y), rntf32(v.z), rntf32(v.w));
            float4 u = *(const float4*)(Bb + (long long)(n0 + r) * ldb + k0 + lk);
            *(float4*)&Bs[r * SSTR + lk] =
                make_float4(rntf32(u.x), rntf32(u.y), rntf32(u.z), rntf32(u.w));
        }
        __syncthreads();

        // ---------------- 4 k-steps of m16n8k8 ----------------
#pragma unroll
        for (int ks = 0; ks < 4; ks++) {
            const int kk = ks * 8;
            uint32_t af[4][4], bf[4][2];
#pragma unroll
            for (int mt = 0; mt < 4; mt++) {
                int r = wm * 64 + mt * 16 + gid;
                af[mt][0] = __float_as_uint(As[(r    ) * SSTR + kk + tig    ]);
                af[mt][1] = __float_as_uint(As[(r + 8) * SSTR + kk + tig    ]);
                af[mt][2] = __float_as_uint(As[(r    ) * SSTR + kk + tig + 4]);
                af[mt][3] = __float_as_uint(As[(r + 8) * SSTR + kk + tig + 4]);
            }
#pragma unroll
            for (int nt = 0; nt < 4; nt++) {
                int cN = wn * 32 + nt * 8 + gid;
                bf[nt][0] = __float_as_uint(Bs[cN * SSTR + kk + tig    ]);
                bf[nt][1] = __float_as_uint(Bs[cN * SSTR + kk + tig + 4]);
            }
#pragma unroll
            for (int mt = 0; mt < 4; mt++)
#pragma unroll
                for (int nt = 0; nt < 4; nt++)
                    mma_tf32(acc[mt][nt], af[mt], bf[nt]);
        }
        __syncthreads();
    }

    // ---------------- epilogue straight from registers ----------------
#pragma unroll
    for (int mt = 0; mt < 4; mt++) {
#pragma unroll
        for (int nt = 0; nt < 4; nt++) {
            const int r0 = m0 + wm * 64 + mt * 16 + gid;
            const int cN = n0 + wn * 32 + nt * 8 + 2 * tig;
#pragma unroll
            for (int half = 0; half < 2; half++) {
                const int r = r0 + half * 8;
                float x = acc[mt][nt][half * 2 + 0];
                float y = acc[mt][nt][half * 2 + 1];
                if (epi == 0) {
                    float2 o = make_float2(x * scale + bias[cN],
                                           y * scale + bias[cN + 1]);
                    *(float2*)&D[dH * zh + (long long)r * ldd + cN] = o;
                } else if (epi == 2) {
                    float2 o = make_float2(x * scale, y * scale);
                    *(float2*)&D[dH * zh + (long long)r * ldd + cN] = o;
                } else if (epi == 1) {
                    // Vt: n = h*256 + d  ->  D[(h*HD+d)*MVID + m]
                    D[(long long)(cN    ) * MVID + r] = x;
                    D[(long long)(cN + 1) * MVID + r] = y;
                } else {
                    // attn scatter: m = b*32+t, n = d
                    long long addr = (long long)zs * pStride
                                   + (long long)(r >> 5) * 16384
                                   + (long long)zh * 8192
                                   + (r & 31) * 256 + cN;
                    *(float2*)&D[addr] = make_float2(x, y);
                }
            }
        }
    }
}

// ---------------------------------------------------------------------------
// Softmax over 64 frames (per video) + transpose: L[h][av][bt] -> Wt[h][bt][av]
// folds in 1/128 for the mean over videos.
// ---------------------------------------------------------------------------
__global__ __launch_bounds__(256) void softmax_t_kernel()
{
    __shared__ float sm[64 * 65];
    __shared__ float red[2][4][64];
    const int h = blockIdx.z, a = blockIdx.y, btc = blockIdx.x;
    const float* L = g_L + ((long long)h * MVID + a * 64) * MTXT + btc * 64;
    float* W = g_Wt + ((long long)h * MTXT + btc * 64) * MVID + a * 64;
    const int tid = threadIdx.x;

#pragma unroll
    for (int i = 0; i < 16; i++) {
        int idx = tid + i * 256;
        int v = idx >> 6, bt = idx & 63;
        sm[v * 65 + bt] = L[(long long)v * MTXT + bt];
    }
    __syncthreads();

    const int bt = tid & 63, vg = tid >> 6;
    float mx = -1e30f;
#pragma unroll
    for (int i = 0; i < 16; i++) mx = fmaxf(mx, sm[(vg * 16 + i) * 65 + bt]);
    red[0][vg][bt] = mx;
    __syncthreads();
    mx = fmaxf(fmaxf(red[0][0][bt], red[0][1][bt]), fmaxf(red[0][2][bt], red[0][3][bt]));
    float sum = 0.0f;
#pragma unroll
    for (int i = 0; i < 16; i++) {
        float e = __expf(sm[(vg * 16 + i) * 65 + bt] - mx);
        sm[(vg * 16 + i) * 65 + bt] = e;
        sum += e;
    }
    red[1][vg][bt] = sum;
    __syncthreads();
    sum = red[1][0][bt] + red[1][1][bt] + red[1][2][bt] + red[1][3][bt];
    const float inv = (1.0f / 128.0f) / sum;
#pragma unroll
    for (int i = 0; i < 16; i++) sm[(vg * 16 + i) * 65 + bt] *= inv;
    __syncthreads();

#pragma unroll
    for (int i = 0; i < 16; i++) {
        int idx = tid + i * 256;
        int btw = idx >> 6, v = idx & 63;
        W[(long long)btw * MVID + v] = sm[v * 65 + btw];
    }
}

// ---------------------------------------------------------------------------
extern "C" void kernel_launch(void* const* d_in, const int* in_sizes, int n_in,
                              void* d_out, int out_size)
{
    const float* text  = (const float*)d_in[0];
    const float* video = (const float*)d_in[1];
    const float* Wq = (const float*)d_in[2];
    const float* bq = (const float*)d_in[3];
    const float* Wk = (const float*)d_in[4];
    const float* bk = (const float*)d_in[5];
    const float* Wv = (const float*)d_in[6];
    const float* bv = (const float*)d_in[7];
    const float* Wo = (const float*)d_in[8];
    const float* bo = (const float*)d_in[9];
    float* out = (float*)d_out;

    float *Qp, *Kp, *Vtp, *Lp, *Wtp, *Pp;
    cudaGetSymbolAddress((void**)&Qp,  g_Q);
    cudaGetSymbolAddress((void**)&Kp,  g_K);
    cudaGetSymbolAddress((void**)&Vtp, g_Vt);
    cudaGetSymbolAddress((void**)&Lp,  g_L);
    cudaGetSymbolAddress((void**)&Wtp, g_Wt);
    cudaGetSymbolAddress((void**)&Pp,  g_part);

    dim3 t(256);

    // Q/K projections (epi0); V projection with per-head transpose (epi1)
    gemm_mma<<<dim3(4, 16, 1), t>>>(text, 512, 0, 0,  Wq, 512, 0, 0,
        bq, Qp, 512, 1, 1, 0, 0, 512, 0, 1.0f);
    gemm_mma<<<dim3(4, 64, 1), t>>>(video, 512, 0, 0, Wk, 512, 0, 0,
        bk, Kp, 512, 1, 1, 0, 0, 512, 0, 1.0f);
    gemm_mma<<<dim3(4, 64, 1), t>>>(video, 512, 0, 0, Wv, 512, 0, 0,
        bv, Vtp, 512, 1, 1, 0, 1, 0, 0, 1.0f);

    // Logits per head: L[av, bt] = (K_h . Q_h) / 16   (epi2)
    gemm_mma<<<dim3(16, 64, 2), t>>>(Kp, 512, 256, 0, Qp, 512, 256, 0,
        nullptr, Lp, 256, 1, 1, 0, 2, MTXT, (long long)MVID * MTXT, 1.0f / 16.0f);

    // Softmax over frames + transpose (+1/128)
    softmax_t_kernel<<<dim3(32, 128, 2), 256>>>();

    // Attention: D[bt, d] = sum_av Wt[bt,av] * Vt[d,av], split-K x8 (epi3)
    gemm_mma<<<dim3(2, 16, 16), t>>>(Wtp, MVID, (long long)MTXT * MVID, KSPL,
        Vtp, MVID, (long long)HD * MVID, KSPL,
        nullptr, Pp, KSPL, NSPLIT, 1, (long long)MTXT * E, 3, 0, 0, 1.0f);

    // Output projection, summing the 8 split-K partials during A-load (epi0)
    gemm_mma<<<dim3(4, 16, 1), t>>>(Pp, 512, 0, 0, Wo, 512, 0, 0,
        bo, out, 512, 1, NSPLIT, (long long)MTXT * E, 0, 512, 0, 1.0f);
}